// round 2
// baseline (speedup 1.0000x reference)
#include <cuda_runtime.h>

// ---------------------------------------------------------------------------
// Problem constants
// ---------------------------------------------------------------------------
#define BSZ   1024
#define TLEN  64
#define SDIM  30
#define DDIM  200
#define HDIM  200
#define EDIM  1024
#define ADIM  6

// ---------------------------------------------------------------------------
// Device scratch (no cudaMalloc allowed)
// ---------------------------------------------------------------------------
__device__ float g_eo[(size_t)BSZ * TLEN * HDIM];   // embed @ w_obs1[200:] + b_obs1

// Packed (k-pair interleaved) weights: element [kp][c] is a 64-bit pair
// (w[2kp][c], w[2kp+1][c]) for fma.rn.f32x2.
__device__ unsigned long long g_gru_wp[100 * 600];
__device__ unsigned long long g_gru_up[100 * 600];
__device__ unsigned long long g_wimg1_p[18 * 200];
__device__ unsigned long long g_wimg2_p[100 * 200];
__device__ unsigned long long g_wobs1d_p[100 * 200];
__device__ unsigned long long g_whp[4 * 100 * 30];  // heads: omean, ostd, imean, istd

typedef unsigned long long ull;

__device__ __forceinline__ ull fma2(ull a, ull b, ull c) {
    ull d;
    asm("fma.rn.f32x2 %0, %1, %2, %3;" : "=l"(d) : "l"(a), "l"(b), "l"(c));
    return d;
}
__device__ __forceinline__ float sum2(ull a) {
    float2 f;
    asm("mov.b64 {%0, %1}, %2;" : "=f"(f.x), "=f"(f.y) : "l"(a));
    return f.x + f.y;
}
__device__ __forceinline__ float elu1(float v) {
    return v > 0.f ? v : (__expf(v) - 1.f);
}
__device__ __forceinline__ float softplus1(float x) {
    return fmaxf(x, 0.f) + log1pf(__expf(-fabsf(x)));
}
__device__ __forceinline__ float sigmoid1(float x) {
    return 1.f / (1.f + __expf(-x));
}

// ---------------------------------------------------------------------------
// Repack (device function, called from eo kernel prologue)
// ---------------------------------------------------------------------------
__device__ __forceinline__ void repack_one(int i,
                                           const float* __restrict__ w_img1,
                                           const float* __restrict__ gru_w,
                                           const float* __restrict__ gru_u,
                                           const float* __restrict__ w_img2,
                                           const float* __restrict__ w_obs1,
                                           const float* __restrict__ w_omean,
                                           const float* __restrict__ w_ostd,
                                           const float* __restrict__ w_imean,
                                           const float* __restrict__ w_istd) {
    if (i < 120000) {
        int p = i & 1, t = i >> 1, c = t % 600, kp = t / 600;
        ((float*)g_gru_wp)[i] = gru_w[(2 * kp + p) * 600 + c];
    } else if (i < 240000) {
        int j = i - 120000;
        int p = j & 1, t = j >> 1, c = t % 600, kp = t / 600;
        ((float*)g_gru_up)[j] = gru_u[(2 * kp + p) * 600 + c];
    } else if (i < 247200) {
        int j = i - 240000;
        int p = j & 1, t = j >> 1, c = t % 200, kp = t / 200;
        ((float*)g_wimg1_p)[j] = w_img1[(2 * kp + p) * 200 + c];
    } else if (i < 287200) {
        int j = i - 247200;
        int p = j & 1, t = j >> 1, c = t % 200, kp = t / 200;
        ((float*)g_wimg2_p)[j] = w_img2[(2 * kp + p) * 200 + c];
    } else if (i < 327200) {
        int j = i - 287200;
        int p = j & 1, t = j >> 1, c = t % 200, kp = t / 200;
        ((float*)g_wobs1d_p)[j] = w_obs1[(2 * kp + p) * 200 + c];
    } else if (i < 351200) {
        int j = i - 327200;
        int p = j & 1, t = j >> 1;
        int s = t % 30, u = t / 30, kp = u % 100, h = u / 100;
        const float* src = (h == 0) ? w_omean : (h == 1) ? w_ostd : (h == 2) ? w_imean : w_istd;
        ((float*)g_whp)[j] = src[(2 * kp + p) * 30 + s];
    }
}

// ---------------------------------------------------------------------------
// Kernel 1: repack prologue + eo GEMM
// g_eo[m][c] = embed_row(m) @ w_obs1[200:1224, :] + b_obs1
// M=65536, K=1024, N=200; BM=64, BN=200, BK=32, 320 threads, tile 8x5
// ---------------------------------------------------------------------------
__global__ __launch_bounds__(320, 1)
void eo_gemm_kernel(const float* __restrict__ embed,
                    const float* __restrict__ w_obs1,
                    const float* __restrict__ b_obs1,
                    const float* __restrict__ w_img1,
                    const float* __restrict__ gru_w,
                    const float* __restrict__ gru_u,
                    const float* __restrict__ w_img2,
                    const float* __restrict__ w_omean,
                    const float* __restrict__ w_ostd,
                    const float* __restrict__ w_imean,
                    const float* __restrict__ w_istd) {
    // ---- repack slice (no dependence on the GEMM below) ----
    for (int i = blockIdx.x * 320 + threadIdx.x; i < 351200; i += 1024 * 320) {
        repack_one(i, w_img1, gru_w, gru_u, w_img2, w_obs1,
                   w_omean, w_ostd, w_imean, w_istd);
    }

    __shared__ __align__(16) float as_f[64 * 32];
    __shared__ __align__(16) float ws_f[32 * 200];
    const ull* as_u = (const ull*)as_f;
    const ull* ws_u = (const ull*)ws_f;

    int tid = threadIdx.x;
    int tx = tid % 40;
    int ty = tid / 40;
    int m0 = blockIdx.x * 64;

    ull acc[8][5];
#pragma unroll
    for (int r = 0; r < 8; r++)
#pragma unroll
        for (int j = 0; j < 5; j++) acc[r][j] = 0ull;

    for (int k0 = 0; k0 < 1024; k0 += 32) {
        __syncthreads();
        for (int idx = tid; idx < 2048; idx += 320) {
            int r = idx >> 5, k = idx & 31;
            as_f[idx] = embed[(size_t)(m0 + r) * 1024 + k0 + k];
        }
        for (int idx = tid; idx < 6400; idx += 320) {
            int k = idx / 200, c = idx % 200;
            ws_f[((k >> 1) * 200 + c) * 2 + (k & 1)] =
                w_obs1[(size_t)(200 + k0 + k) * 200 + c];
        }
        __syncthreads();
#pragma unroll
        for (int kp = 0; kp < 16; kp++) {
            ull wv[5];
#pragma unroll
            for (int j = 0; j < 5; j++) wv[j] = ws_u[kp * 200 + tx * 5 + j];
#pragma unroll
            for (int r = 0; r < 8; r++) {
                ull av = as_u[(ty * 8 + r) * 16 + kp];
#pragma unroll
                for (int j = 0; j < 5; j++) acc[r][j] = fma2(av, wv[j], acc[r][j]);
            }
        }
    }

#pragma unroll
    for (int r = 0; r < 8; r++) {
        int m = m0 + ty * 8 + r;
#pragma unroll
        for (int j = 0; j < 5; j++) {
            int c = tx * 5 + j;
            g_eo[(size_t)m * 200 + c] = sum2(acc[r][j]) + b_obs1[c];
        }
    }
}

// ---------------------------------------------------------------------------
// Kernel 2: persistent recurrent kernel.
// 128 CTAs x 8 batch rows, 512 threads (16 warps), T=64 internal loop.
// Threads 0..399: (c, half) with c = tid%200, half = tid/200; 4 rows each.
// ---------------------------------------------------------------------------
__global__ __launch_bounds__(512, 1)
void rssm_recur_kernel(const float* __restrict__ action,
                       const float* __restrict__ noise_prior,
                       const float* __restrict__ noise_post,
                       const float* __restrict__ b_img1,
                       const float* __restrict__ gru_b,
                       const float* __restrict__ gru_rb,
                       const float* __restrict__ b_img2,
                       const float* __restrict__ b_imean,
                       const float* __restrict__ b_istd,
                       const float* __restrict__ b_omean,
                       const float* __restrict__ b_ostd,
                       float* __restrict__ out) {
    __shared__ __align__(16) float sm[7680];
    float* s_in = sm;            // [8][40]  stoch(30)+action(6)+pad
    float* det0 = sm + 320;      // [8][200]
    float* det1 = sm + 1920;     // [8][200]
    float* s_x  = sm + 3520;     // [8][200] img1-out, later x2
    float* s_xo = sm + 5120;     // [8][200]
    float* s_hd = sm + 6720;     // [4][8][30]

    const int tid = threadIdx.x;
    const int b0 = blockIdx.x * 8;

    const bool is_mm = (tid < 400);
    const int c = tid % 200;
    const int half = tid / 200;          // 0 or 1 (only valid when is_mm)
    const int rbase = half * 4;          // first of 4 rows

    // ---- hoisted per-thread constants ----
    float c_b1 = 0.f, c_bz = 0.f, c_br = 0.f, c_bxh = 0.f, c_bhh = 0.f, c_b2 = 0.f;
    if (is_mm) {
        c_b1  = b_img1[c];
        c_bz  = gru_b[c] + gru_rb[c];
        c_br  = gru_b[200 + c] + gru_rb[200 + c];
        c_bxh = gru_b[400 + c];
        c_bhh = gru_rb[400 + c];
        c_b2  = b_img2[c];
    }
    // head thread constants (tid < 240): half_h, h, s
    int hh_half = 0, hh_h = 0, hh_s = 0; float c_hb = 0.f;
    if (tid < 240) {
        hh_half = tid / 120;
        int rem = tid % 120;
        hh_h = rem / 30;
        hh_s = rem % 30;
        c_hb = (hh_h == 0) ? b_omean[hh_s] : (hh_h == 1) ? b_ostd[hh_s]
             : (hh_h == 2) ? b_imean[hh_s] : b_istd[hh_s];
    }

    // ---- init carry + action[0] ----
    for (int i = tid; i < 320; i += 512) s_in[i] = 0.f;
    for (int i = tid; i < 1600; i += 512) det0[i] = 0.f;
    if (tid < 48) {
        int r = tid / 6, j = tid % 6;
        s_in[r * 40 + 30 + j] = action[(size_t)(b0 + r) * (TLEN * ADIM) + j];
    }

    float* pd = det0;
    float* pn = det1;
    __syncthreads();

    for (int t = 0; t < TLEN; ++t) {
        // ================= P1: x = elu([stoch,action] @ w_img1 + b) =========
        if (is_mm) {
            ull acc[4];
#pragma unroll
            for (int r = 0; r < 4; r++) acc[r] = 0ull;
#pragma unroll
            for (int kp = 0; kp < 18; kp++) {
                ull w = __ldg(&g_wimg1_p[kp * 200 + c]);
#pragma unroll
                for (int r = 0; r < 4; r++) {
                    ull in2 = *reinterpret_cast<const ull*>(s_in + (rbase + r) * 40 + 2 * kp);
                    acc[r] = fma2(in2, w, acc[r]);
                }
            }
#pragma unroll
            for (int r = 0; r < 4; r++)
                s_x[(rbase + r) * 200 + c] = elu1(sum2(acc[r]) + c_b1);
        }
        __syncthreads();

        // ================= P2+P3: GRU + gates fused =========================
        float eo_r[4];   // prefetch g_eo for P4 (hide L2 latency under GRU)
        if (is_mm) {
#pragma unroll
            for (int r = 0; r < 4; r++)
                eo_r[r] = __ldg(&g_eo[((size_t)(b0 + rbase + r) * TLEN + t) * 200 + c]);

            ull az[4], ar[4], axh[4], ahh[4];
#pragma unroll
            for (int r = 0; r < 4; r++) { az[r] = 0; ar[r] = 0; axh[r] = 0; ahh[r] = 0; }
            const ull* pw = g_gru_wp + c;
            const ull* pu = g_gru_up + c;
            const float* xb = s_x + rbase * 200;
            const float* db = pd + rbase * 200;
#pragma unroll 2
            for (int kp = 0; kp < 100; kp++) {
                ull wz = __ldg(pw + kp * 600);
                ull wr = __ldg(pw + kp * 600 + 200);
                ull wh = __ldg(pw + kp * 600 + 400);
                ull uz = __ldg(pu + kp * 600);
                ull ur = __ldg(pu + kp * 600 + 200);
                ull uh = __ldg(pu + kp * 600 + 400);
#pragma unroll
                for (int r = 0; r < 4; r++) {
                    ull x2 = *reinterpret_cast<const ull*>(xb + r * 200 + 2 * kp);
                    ull d2 = *reinterpret_cast<const ull*>(db + r * 200 + 2 * kp);
                    az[r]  = fma2(x2, wz, az[r]);
                    ar[r]  = fma2(x2, wr, ar[r]);
                    axh[r] = fma2(x2, wh, axh[r]);
                    az[r]  = fma2(d2, uz, az[r]);
                    ar[r]  = fma2(d2, ur, ar[r]);
                    ahh[r] = fma2(d2, uh, ahh[r]);
                }
            }
            // fused gate epilogue (this thread owns (rbase+r, c) fully)
#pragma unroll
            for (int r = 0; r < 4; r++) {
                int rr = rbase + r;
                float z  = sigmoid1(sum2(az[r]) + c_bz);
                float rg = sigmoid1(sum2(ar[r]) + c_br);
                float a  = sum2(axh[r]) + c_bxh + rg * (sum2(ahh[r]) + c_bhh);
                float e2 = __expf(2.f * a);
                float th = 1.f - 2.f / (e2 + 1.f);
                float dn = z * pd[rr * 200 + c] + (1.f - z) * th;
                pn[rr * 200 + c] = dn;
                float* orow = out + ((size_t)(b0 + rr) * TLEN + t) * 580;
                orow[90 + c]  = dn;
                orow[380 + c] = dn;
            }
        }
        __syncthreads();

        // ================= P4: x2 / xo ======================================
        if (is_mm) {
            ull aa[4], ab[4];
#pragma unroll
            for (int r = 0; r < 4; r++) { aa[r] = 0; ab[r] = 0; }
            const ull* pa = g_wimg2_p + c;
            const ull* pb = g_wobs1d_p + c;
            const float* db = pn + rbase * 200;
#pragma unroll 2
            for (int kp = 0; kp < 100; kp++) {
                ull wa = __ldg(pa + kp * 200);
                ull wb = __ldg(pb + kp * 200);
#pragma unroll
                for (int r = 0; r < 4; r++) {
                    ull d2 = *reinterpret_cast<const ull*>(db + r * 200 + 2 * kp);
                    aa[r] = fma2(d2, wa, aa[r]);
                    ab[r] = fma2(d2, wb, ab[r]);
                }
            }
#pragma unroll
            for (int r = 0; r < 4; r++) {
                int rr = rbase + r;
                s_x[rr * 200 + c]  = elu1(sum2(aa[r]) + c_b2);
                s_xo[rr * 200 + c] = elu1(sum2(ab[r]) + eo_r[r]);  // eo has b_obs1
            }
        }
        __syncthreads();

        // ================= P5: 4 heads (+ action prefetch by idle threads) ==
        if (tid < 240) {
            const ull* wp = g_whp + hh_h * 3000 + hh_s;
            const float* src = ((hh_h < 2) ? s_xo : s_x) + hh_half * 800;
            ull acc[4];
#pragma unroll
            for (int r = 0; r < 4; r++) acc[r] = 0ull;
#pragma unroll 4
            for (int kp = 0; kp < 100; kp++) {
                ull w = __ldg(wp + kp * 30);
#pragma unroll
                for (int r = 0; r < 4; r++) {
                    ull v2 = *reinterpret_cast<const ull*>(src + r * 200 + 2 * kp);
                    acc[r] = fma2(v2, w, acc[r]);
                }
            }
#pragma unroll
            for (int r = 0; r < 4; r++) {
                int rr = hh_half * 4 + r;
                float v = sum2(acc[r]) + c_hb;
                float* orow = out + ((size_t)(b0 + rr) * TLEN + t) * 580;
                float res;
                if (hh_h == 0)      { res = v;                   orow[hh_s]       = res; }
                else if (hh_h == 1) { res = softplus1(v);        orow[30 + hh_s]  = res; }
                else if (hh_h == 2) { res = v;                   orow[290 + hh_s] = res; }
                else                { res = softplus1(v) + 0.1f; orow[320 + hh_s] = res; }
                s_hd[hh_h * 240 + rr * 30 + hh_s] = res;
            }
        } else if (tid >= 448 && tid < 496 && t + 1 < TLEN) {
            // prefetch action[t+1] into s_in (slots untouched by P6)
            int idx = tid - 448;
            int r = idx / 6, j = idx % 6;
            s_in[r * 40 + 30 + j] =
                action[(size_t)(b0 + r) * (TLEN * ADIM) + (t + 1) * ADIM + j];
        }
        __syncthreads();

        // ================= P6: samples + stoch carry ========================
        if (tid < 240) {
            int r = tid / 30, s = tid - r * 30;
            size_t nidx = (size_t)t * (BSZ * SDIM) + (size_t)(b0 + r) * SDIM + s;
            float om  = s_hd[r * 30 + s];
            float osd = s_hd[240 + r * 30 + s];
            float ost = om + osd * __ldg(&noise_post[nidx]);
            float pm  = s_hd[480 + r * 30 + s];
            float psd = s_hd[720 + r * 30 + s];
            float pst = pm + psd * __ldg(&noise_prior[nidx]);
            float* orow = out + ((size_t)(b0 + r) * TLEN + t) * 580;
            orow[60 + s]  = ost;
            orow[350 + s] = pst;
            s_in[r * 40 + s] = ost;
        }

        { float* tmp = pd; pd = pn; pn = tmp; }
        __syncthreads();
    }
}

// ---------------------------------------------------------------------------
// Launch
// ---------------------------------------------------------------------------
extern "C" void kernel_launch(void* const* d_in, const int* in_sizes, int n_in,
                              void* d_out, int out_size) {
    const float* embed       = (const float*)d_in[0];
    const float* action      = (const float*)d_in[1];
    const float* noise_prior = (const float*)d_in[2];
    const float* noise_post  = (const float*)d_in[3];
    const float* w_img1      = (const float*)d_in[4];
    const float* b_img1      = (const float*)d_in[5];
    const float* gru_w       = (const float*)d_in[6];
    const float* gru_u       = (const float*)d_in[7];
    const float* gru_b       = (const float*)d_in[8];
    const float* gru_rb      = (const float*)d_in[9];
    const float* w_img2      = (const float*)d_in[10];
    const float* b_img2      = (const float*)d_in[11];
    const float* w_imean     = (const float*)d_in[12];
    const float* b_imean     = (const float*)d_in[13];
    const float* w_istd      = (const float*)d_in[14];
    const float* b_istd      = (const float*)d_in[15];
    const float* w_obs1      = (const float*)d_in[16];
    const float* b_obs1      = (const float*)d_in[17];
    const float* w_omean     = (const float*)d_in[18];
    const float* b_omean     = (const float*)d_in[19];
    const float* w_ostd      = (const float*)d_in[20];
    const float* b_ostd      = (const float*)d_in[21];
    float* out = (float*)d_out;

    eo_gemm_kernel<<<BSZ * TLEN / 64, 320>>>(embed, w_obs1, b_obs1,
                                             w_img1, gru_w, gru_u, w_img2,
                                             w_omean, w_ostd, w_imean, w_istd);
    rssm_recur_kernel<<<BSZ / 8, 512>>>(action, noise_prior, noise_post,
                                        b_img1, gru_b, gru_rb, b_img2,
                                        b_imean, b_istd, b_omean, b_ostd, out);
}

// round 3
// speedup vs baseline: 1.3867x; 1.3867x over previous
#include <cuda_runtime.h>

#define BSZ   1024
#define TLEN  64
#define SDIM  30
#define DDIM  200
#define HDIM  200
#define EDIM  1024
#define ADIM  6

typedef unsigned long long ull;

// ---------------------------------------------------------------------------
// Device scratch
// ---------------------------------------------------------------------------
__device__ float g_eo[(size_t)BSZ * TLEN * HDIM];   // embed @ w_obs1[200:] + b_obs1

// k-quad packed weights (float4 = 4 consecutive k values for one output col)
__device__ float4 g_gru4[6 * 50 * 200];  // [stream][kq][c]; st: Wz,Wr,Wh,Uz,Ur,Uh
__device__ float4 g_p4[2 * 50 * 200];    // [mat][kq][c]; mat: img2, obs1d
__device__ float4 g_i14[9 * 200];        // img1 [kq][c], K=36
__device__ float4 g_h4[4 * 50 * 30];     // heads [h][kq][s]

// ---------------------------------------------------------------------------
// Helpers
// ---------------------------------------------------------------------------
__device__ __forceinline__ ull fma2(ull a, ull b, ull c) {
    ull d;
    asm("fma.rn.f32x2 %0, %1, %2, %3;" : "=l"(d) : "l"(a), "l"(b), "l"(c));
    return d;
}
__device__ __forceinline__ float sum2(ull a) {
    float2 f;
    asm("mov.b64 {%0, %1}, %2;" : "=f"(f.x), "=f"(f.y) : "l"(a));
    return f.x + f.y;
}
__device__ __forceinline__ ulonglong2 ldg2(const float4* p) {
    return __ldg(reinterpret_cast<const ulonglong2*>(p));
}
__device__ __forceinline__ ulonglong2 lds2(const float* p) {
    return *reinterpret_cast<const ulonglong2*>(p);
}
__device__ __forceinline__ float elu1(float v) {
    return v > 0.f ? v : (__expf(v) - 1.f);
}
__device__ __forceinline__ float softplus1(float x) {
    return fmaxf(x, 0.f) + log1pf(__expf(-fabsf(x)));
}
__device__ __forceinline__ float sigmoid1(float x) {
    return 1.f / (1.f + __expf(-x));
}

// ---------------------------------------------------------------------------
// Repack: k-quad layouts (one float per index i)
// ---------------------------------------------------------------------------
__device__ __forceinline__ void repack_one(int i,
                                           const float* __restrict__ w_img1,
                                           const float* __restrict__ gru_w,
                                           const float* __restrict__ gru_u,
                                           const float* __restrict__ w_img2,
                                           const float* __restrict__ w_obs1,
                                           const float* __restrict__ w_omean,
                                           const float* __restrict__ w_ostd,
                                           const float* __restrict__ w_imean,
                                           const float* __restrict__ w_istd) {
    if (i < 240000) {                       // GRU 6 streams
        int f = i & 3, q = i >> 2;
        int st = q / 10000, rem = q % 10000, kq = rem / 200, cc = rem % 200;
        int k = 4 * kq + f;
        float v = (st < 3) ? gru_w[k * 600 + st * 200 + cc]
                           : gru_u[k * 600 + (st - 3) * 200 + cc];
        ((float*)g_gru4)[i] = v;
    } else if (i < 320000) {                // img2 / obs1d
        int j = i - 240000;
        int f = j & 3, q = j >> 2;
        int mat = q / 10000, rem = q % 10000, kq = rem / 200, cc = rem % 200;
        int k = 4 * kq + f;
        ((float*)g_p4)[j] = (mat == 0) ? w_img2[k * 200 + cc] : w_obs1[k * 200 + cc];
    } else if (i < 327200) {                // img1
        int j = i - 320000;
        int f = j & 3, q = j >> 2;
        int kq = q / 200, cc = q % 200;
        int k = 4 * kq + f;                 // k < 36 always
        ((float*)g_i14)[j] = w_img1[k * 200 + cc];
    } else if (i < 351200) {                // heads
        int j = i - 327200;
        int f = j & 3, q = j >> 2;
        int h = q / 1500, rem = q % 1500, kq = rem / 30, s = rem % 30;
        int k = 4 * kq + f;
        const float* src = (h == 0) ? w_omean : (h == 1) ? w_ostd
                         : (h == 2) ? w_imean : w_istd;
        ((float*)g_h4)[j] = src[k * 30 + s];
    }
}

// ---------------------------------------------------------------------------
// Kernel 1: repack + eo GEMM (register double-buffered prefetch)
// ---------------------------------------------------------------------------
__global__ __launch_bounds__(320, 1)
void eo_gemm_kernel(const float* __restrict__ embed,
                    const float* __restrict__ w_obs1,
                    const float* __restrict__ b_obs1,
                    const float* __restrict__ w_img1,
                    const float* __restrict__ gru_w,
                    const float* __restrict__ gru_u,
                    const float* __restrict__ w_img2,
                    const float* __restrict__ w_omean,
                    const float* __restrict__ w_ostd,
                    const float* __restrict__ w_imean,
                    const float* __restrict__ w_istd) {
    for (int i = blockIdx.x * 320 + threadIdx.x; i < 351200; i += 1024 * 320) {
        repack_one(i, w_img1, gru_w, gru_u, w_img2, w_obs1,
                   w_omean, w_ostd, w_imean, w_istd);
    }

    __shared__ __align__(16) float as_f[64 * 32];
    __shared__ __align__(16) float ws_f[32 * 200];
    const ull* as_u = (const ull*)as_f;
    const ull* ws_u = (const ull*)ws_f;

    const int tid = threadIdx.x;
    const int tx = tid % 40;
    const int ty = tid / 40;
    const int m0 = blockIdx.x * 64;

    ull acc[8][5];
#pragma unroll
    for (int r = 0; r < 8; r++)
#pragma unroll
        for (int j = 0; j < 5; j++) acc[r][j] = 0ull;

    // prefetch registers
    float4 aP[2];
    float4 wP[5];
    const bool aPred = (tid < 256);

    // ---- preload chunk 0 ----
    {
        if (aPred) {
#pragma unroll
            for (int p = 0; p < 2; p++) {
                int q = tid + 256 * p;
                int r = q >> 3, qq = q & 7;
                aP[p] = *reinterpret_cast<const float4*>(
                    embed + (size_t)(m0 + r) * 1024 + qq * 4);
            }
        }
#pragma unroll
        for (int p = 0; p < 5; p++) {
            int q = tid + 320 * p;
            int k = q / 50, c4 = (q % 50) * 4;
            wP[p] = *reinterpret_cast<const float4*>(
                w_obs1 + (size_t)(200 + k) * 200 + c4);
        }
    }

    for (int chunk = 0; chunk < 32; chunk++) {
        __syncthreads();
        // store prefetched chunk to smem
        if (aPred) {
#pragma unroll
            for (int p = 0; p < 2; p++) {
                int q = tid + 256 * p;
                int r = q >> 3, qq = q & 7;
                *reinterpret_cast<float4*>(as_f + r * 32 + qq * 4) = aP[p];
            }
        }
#pragma unroll
        for (int p = 0; p < 5; p++) {
            int q = tid + 320 * p;
            int k = q / 50, c4 = (q % 50) * 4;
            float vv[4] = {wP[p].x, wP[p].y, wP[p].z, wP[p].w};
#pragma unroll
            for (int j = 0; j < 4; j++)
                ws_f[((k >> 1) * 200 + c4 + j) * 2 + (k & 1)] = vv[j];
        }
        __syncthreads();

        // prefetch next chunk
        if (chunk < 31) {
            int k0 = (chunk + 1) * 32;
            if (aPred) {
#pragma unroll
                for (int p = 0; p < 2; p++) {
                    int q = tid + 256 * p;
                    int r = q >> 3, qq = q & 7;
                    aP[p] = *reinterpret_cast<const float4*>(
                        embed + (size_t)(m0 + r) * 1024 + k0 + qq * 4);
                }
            }
#pragma unroll
            for (int p = 0; p < 5; p++) {
                int q = tid + 320 * p;
                int k = q / 50, c4 = (q % 50) * 4;
                wP[p] = *reinterpret_cast<const float4*>(
                    w_obs1 + (size_t)(200 + k0 + k) * 200 + c4);
            }
        }

        // compute on current chunk
#pragma unroll
        for (int kp = 0; kp < 16; kp++) {
            ull wv[5];
#pragma unroll
            for (int j = 0; j < 5; j++) wv[j] = ws_u[kp * 200 + tx * 5 + j];
#pragma unroll
            for (int r = 0; r < 8; r++) {
                ull av = as_u[(ty * 8 + r) * 16 + kp];
#pragma unroll
                for (int j = 0; j < 5; j++) acc[r][j] = fma2(av, wv[j], acc[r][j]);
            }
        }
    }

#pragma unroll
    for (int r = 0; r < 8; r++) {
        int m = m0 + ty * 8 + r;
#pragma unroll
        for (int j = 0; j < 5; j++) {
            int cc = tx * 5 + j;
            g_eo[(size_t)m * 200 + cc] = sum2(acc[r][j]) + b_obs1[cc];
        }
    }
}

// ---------------------------------------------------------------------------
// Kernel 2: persistent recurrent kernel — gate-split layout.
// 128 CTAs x 8 batch rows, 800 threads: tid = g*200 + c, g in 0..3.
// g0: z = x@Wz + d@Uz ; g1: r ; g2: x@Wh ; g3: d@Uh.  dup=1 weight loads.
// ---------------------------------------------------------------------------
__global__ __launch_bounds__(800, 1)
void rssm_recur_kernel(const float* __restrict__ action,
                       const float* __restrict__ noise_prior,
                       const float* __restrict__ noise_post,
                       const float* __restrict__ b_img1,
                       const float* __restrict__ gru_b,
                       const float* __restrict__ gru_rb,
                       const float* __restrict__ b_img2,
                       const float* __restrict__ b_imean,
                       const float* __restrict__ b_istd,
                       const float* __restrict__ b_omean,
                       const float* __restrict__ b_ostd,
                       float* __restrict__ out) {
    __shared__ __align__(16) float sm[15680];
    float* s_in = sm;            // [8][40]
    float* det0 = sm + 320;      // [8][200]
    float* det1 = sm + 1920;     // [8][200]
    float* s_x  = sm + 3520;     // [8][200]
    float* s_xo = sm + 5120;     // [8][200]
    float* s_eo = sm + 6720;     // [8][200]
    float* s_hd = sm + 8320;     // [4][8][30]
    float* s_g  = sm + 9280;     // [4][8][200] gate exchange / P4 partials

    const int tid = threadIdx.x;
    const int b0 = blockIdx.x * 8;
    const int g = tid / 200;
    const int c = tid % 200;

    // ---- P2 stream params ----
    const int st1 = (g < 3) ? g : 5;
    const bool has2 = (g < 2);
    const float4* p1 = g_gru4 + st1 * 10000 + c;
    const float4* p2 = g_gru4 + (3 + g) * 10000 + c;
    float gbias = (g == 0) ? gru_b[c] + gru_rb[c]
                : (g == 1) ? gru_b[200 + c] + gru_rb[200 + c]
                : (g == 2) ? gru_b[400 + c] : gru_rb[400 + c];

    // ---- P4 params ----
    const int p4ko = (g & 1) * 25;
    const float4* p4w = g_p4 + ((g >> 1) * 50 + p4ko) * 200 + c;

    // ---- P1 params ----
    const float c_b1 = (g < 2) ? b_img1[c] : 0.f;

    // ---- P5 params ----
    int p5q = 0, p5h = 0, p5s = 0; float c_hb = 0.f;
    if (tid < 480) {
        p5q = tid / 120;
        int rem = tid % 120;
        p5h = rem / 30;
        p5s = rem % 30;
        c_hb = (p5h == 0) ? b_omean[p5s] : (p5h == 1) ? b_ostd[p5s]
             : (p5h == 2) ? b_imean[p5s] : b_istd[p5s];
    }

    // ---- init ----
    for (int i = tid; i < 320; i += 800) s_in[i] = 0.f;
    for (int i = tid; i < 1600; i += 800) det0[i] = 0.f;
    if (tid < 48) {
        int r = tid / 6, j = tid % 6;
        s_in[r * 40 + 30 + j] = action[(size_t)(b0 + r) * (TLEN * ADIM) + j];
    }
    float* pd = det0;
    float* pn = det1;
    __syncthreads();

    for (int t = 0; t < TLEN; ++t) {
        // ============ P1: x = elu([stoch,action]@W1 + b)  |  eo load ========
        if (g < 2) {
            const int rb = g * 4;
            ull acc[4];
#pragma unroll
            for (int j = 0; j < 4; j++) acc[j] = 0ull;
#pragma unroll
            for (int kq = 0; kq < 9; kq++) {
                ulonglong2 w = ldg2(g_i14 + kq * 200 + c);
#pragma unroll
                for (int j = 0; j < 4; j++) {
                    ulonglong2 v = lds2(s_in + (rb + j) * 40 + 4 * kq);
                    acc[j] = fma2(v.x, w.x, acc[j]);
                    acc[j] = fma2(v.y, w.y, acc[j]);
                }
            }
#pragma unroll
            for (int j = 0; j < 4; j++)
                s_x[(rb + j) * 200 + c] = elu1(sum2(acc[j]) + c_b1);
        } else {
            int tid2 = tid - 400;
#pragma unroll
            for (int i = 0; i < 4; i++) {
                int e = tid2 + 400 * i;
                int r = e / 200, cc = e - r * 200;
                s_eo[e] = __ldg(&g_eo[((size_t)(b0 + r) * TLEN + t) * 200 + cc]);
            }
        }
        __syncthreads();

        // ============ P2: one GRU stream per g-group ========================
        {
            const float* s1 = (g < 3) ? s_x : pd;
            ull acc[8];
#pragma unroll
            for (int r = 0; r < 8; r++) acc[r] = 0ull;
#pragma unroll 2
            for (int kq = 0; kq < 50; kq++) {
                ulonglong2 w1 = ldg2(p1 + kq * 200);
                ulonglong2 w2;
                if (has2) w2 = ldg2(p2 + kq * 200);
#pragma unroll
                for (int r = 0; r < 8; r++) {
                    ulonglong2 v1 = lds2(s1 + r * 200 + 4 * kq);
                    acc[r] = fma2(v1.x, w1.x, acc[r]);
                    acc[r] = fma2(v1.y, w1.y, acc[r]);
                    if (has2) {
                        ulonglong2 v2 = lds2(pd + r * 200 + 4 * kq);
                        acc[r] = fma2(v2.x, w2.x, acc[r]);
                        acc[r] = fma2(v2.y, w2.y, acc[r]);
                    }
                }
            }
#pragma unroll
            for (int r = 0; r < 8; r++)
                s_g[g * 1600 + r * 200 + c] = sum2(acc[r]) + gbias;
        }
        __syncthreads();

        // ============ P3: gates, deter_n ====================================
#pragma unroll
        for (int i = 0; i < 2; i++) {
            int idx = tid + 800 * i;
            float z  = sigmoid1(s_g[idx]);
            float rg = sigmoid1(s_g[1600 + idx]);
            float a  = s_g[3200 + idx] + rg * s_g[4800 + idx];
            float e2 = __expf(2.f * a);
            float th = 1.f - 2.f / (e2 + 1.f);
            float dn = z * pd[idx] + (1.f - z) * th;
            pn[idx] = dn;
            int r = idx / 200, cc = idx - r * 200;
            float* orow = out + ((size_t)(b0 + r) * TLEN + t) * 580;
            orow[90 + cc]  = dn;
            orow[380 + cc] = dn;
        }
        __syncthreads();

        // ============ P4 partials: (mat, k-half) per g ======================
        {
            ull acc[8];
#pragma unroll
            for (int r = 0; r < 8; r++) acc[r] = 0ull;
#pragma unroll 2
            for (int kq = 0; kq < 25; kq++) {
                ulonglong2 w = ldg2(p4w + kq * 200);
#pragma unroll
                for (int r = 0; r < 8; r++) {
                    ulonglong2 v = lds2(pn + r * 200 + 4 * (p4ko + kq));
                    acc[r] = fma2(v.x, w.x, acc[r]);
                    acc[r] = fma2(v.y, w.y, acc[r]);
                }
            }
#pragma unroll
            for (int r = 0; r < 8; r++)
                s_g[g * 1600 + r * 200 + c] = sum2(acc[r]);
        }
        __syncthreads();

        // ============ P4 epilogue: x2 / xo ==================================
#pragma unroll
        for (int i = 0; i < 4; i++) {
            int o = tid + 800 * i;        // 0..3199
            int m = o / 1600, e = o - m * 1600;
            float sum = s_g[m * 3200 + e] + s_g[m * 3200 + 1600 + e];
            if (m == 0) s_x[e]  = elu1(sum + __ldg(&b_img2[e % 200]));
            else        s_xo[e] = elu1(sum + s_eo[e]);   // eo includes b_obs1
        }
        __syncthreads();

        // ============ P5: 4 heads (+ action prefetch) =======================
        if (tid < 480) {
            const float4* pw = g_h4 + p5h * 1500 + p5s;
            const float* src = (p5h < 2) ? s_xo : s_x;
            const int r0 = 2 * p5q;
            ull a0 = 0ull, a1 = 0ull;
#pragma unroll 2
            for (int kq = 0; kq < 50; kq++) {
                ulonglong2 w = ldg2(pw + kq * 30);
                ulonglong2 v0 = lds2(src + r0 * 200 + 4 * kq);
                a0 = fma2(v0.x, w.x, a0);
                a0 = fma2(v0.y, w.y, a0);
                ulonglong2 v1 = lds2(src + (r0 + 1) * 200 + 4 * kq);
                a1 = fma2(v1.x, w.x, a1);
                a1 = fma2(v1.y, w.y, a1);
            }
#pragma unroll
            for (int j = 0; j < 2; j++) {
                int rr = r0 + j;
                float v = sum2(j == 0 ? a0 : a1) + c_hb;
                float* orow = out + ((size_t)(b0 + rr) * TLEN + t) * 580;
                float res;
                if (p5h == 0)      { res = v;                   orow[p5s]       = res; }
                else if (p5h == 1) { res = softplus1(v);        orow[30 + p5s]  = res; }
                else if (p5h == 2) { res = v;                   orow[290 + p5s] = res; }
                else               { res = softplus1(v) + 0.1f; orow[320 + p5s] = res; }
                s_hd[p5h * 240 + rr * 30 + p5s] = res;
            }
        } else if (tid >= 480 && tid < 528 && t + 1 < TLEN) {
            int idx = tid - 480;
            int r = idx / 6, j = idx % 6;
            s_in[r * 40 + 30 + j] =
                action[(size_t)(b0 + r) * (TLEN * ADIM) + (t + 1) * ADIM + j];
        }
        __syncthreads();

        // ============ P6: samples + stoch carry =============================
        if (tid < 240) {
            int r = tid / 30, s = tid - r * 30;
            size_t nidx = (size_t)t * (BSZ * SDIM) + (size_t)(b0 + r) * SDIM + s;
            float om  = s_hd[r * 30 + s];
            float osd = s_hd[240 + r * 30 + s];
            float ost = om + osd * __ldg(&noise_post[nidx]);
            float pm  = s_hd[480 + r * 30 + s];
            float psd = s_hd[720 + r * 30 + s];
            float pst = pm + psd * __ldg(&noise_prior[nidx]);
            float* orow = out + ((size_t)(b0 + r) * TLEN + t) * 580;
            orow[60 + s]  = ost;
            orow[350 + s] = pst;
            s_in[r * 40 + s] = ost;
        }

        { float* tmp = pd; pd = pn; pn = tmp; }
        __syncthreads();
    }
}

// ---------------------------------------------------------------------------
// Launch
// ---------------------------------------------------------------------------
extern "C" void kernel_launch(void* const* d_in, const int* in_sizes, int n_in,
                              void* d_out, int out_size) {
    const float* embed       = (const float*)d_in[0];
    const float* action      = (const float*)d_in[1];
    const float* noise_prior = (const float*)d_in[2];
    const float* noise_post  = (const float*)d_in[3];
    const float* w_img1      = (const float*)d_in[4];
    const float* b_img1      = (const float*)d_in[5];
    const float* gru_w       = (const float*)d_in[6];
    const float* gru_u       = (const float*)d_in[7];
    const float* gru_b       = (const float*)d_in[8];
    const float* gru_rb      = (const float*)d_in[9];
    const float* w_img2      = (const float*)d_in[10];
    const float* b_img2      = (const float*)d_in[11];
    const float* w_imean     = (const float*)d_in[12];
    const float* b_imean     = (const float*)d_in[13];
    const float* w_istd      = (const float*)d_in[14];
    const float* b_istd      = (const float*)d_in[15];
    const float* w_obs1      = (const float*)d_in[16];
    const float* b_obs1      = (const float*)d_in[17];
    const float* w_omean     = (const float*)d_in[18];
    const float* b_omean     = (const float*)d_in[19];
    const float* w_ostd      = (const float*)d_in[20];
    const float* b_ostd      = (const float*)d_in[21];
    float* out = (float*)d_out;

    eo_gemm_kernel<<<BSZ * TLEN / 64, 320>>>(embed, w_obs1, b_obs1,
                                             w_img1, gru_w, gru_u, w_img2,
                                             w_omean, w_ostd, w_imean, w_istd);
    rssm_recur_kernel<<<BSZ / 8, 800>>>(action, noise_prior, noise_post,
                                        b_img1, gru_b, gru_rb, b_img2,
                                        b_imean, b_istd, b_omean, b_ostd, out);
}